// round 4
// baseline (speedup 1.0000x reference)
#include <cuda_runtime.h>

// reset_layer: x (16,2000,2000) f32, leftm (10,10), rightm (10,10), bs=10.
// out[b, jH*200+hc, jW*200+wc] = x[...] + sum_{iH,iW} R[iH,jH]*L[jW,iW]*x[b, iH*200+hc, iW*200+wc]
//
// Two-stage fused (20 FMA/element):
//   stage1: Y[iH][jW] = sum_iW L[jW,iW] * X[iH][iW]
//   stage2: Z[jH][jW] = X[jH][jW] + sum_iH R[iH,jH] * Y[iH][jW]
//
// R3 change: occupancy 40 -> 60 warps/SM. 1 pixel per thread (scalar), which
// cuts live registers to ~30, allowing __launch_bounds__(640, 3). smem down to
// 25.6 KB/block. Matrices stay in __constant__ (LDCU path, R2 win).

#define NBATCH   16
#define HPIX     2000
#define WPIX     2000
#define HC       200
#define WC       200
#define PIX_TOTAL (NBATCH * HC * WC)      // 640000
#define PIX_PER_BLOCK 64
#define THREADS  640
#define SMEM_BYTES (100 * PIX_PER_BLOCK * 4)   // 25600 B

__constant__ float cL[100];
__constant__ float cR[100];

extern "C" __global__ void __launch_bounds__(THREADS, 3)
reset_layer_kernel(const float* __restrict__ x,
                   float* __restrict__ out)
{
    extern __shared__ float smem[];
    float* Ys = smem;   // [10 roles][10 jW][64 pixels]

    const int tid  = threadIdx.x;
    const int w    = tid >> 5;
    const int lane = tid & 31;
    const int s    = w >> 1;                      // role 0..9 (iH then jW)
    const int t    = ((w & 1) << 5) | lane;       // pixel slot 0..63

    const int p  = blockIdx.x * PIX_PER_BLOCK + t;
    const int b  = p / (HC * WC);
    const int r  = p - b * (HC * WC);
    const int hc = r / WC;
    const int wc = r - hc * WC;

    // ---------------- stage 1: this role's iH = s ----------------
    const float* xrow = x + (size_t)(b * HPIX + s * HC + hc) * WPIX + wc;

    float Xv[10];
#pragma unroll
    for (int iW = 0; iW < 10; iW++)
        Xv[iW] = __ldg(xrow + iW * WC);

#pragma unroll
    for (int jW = 0; jW < 10; jW++) {
        float acc = 0.f;
#pragma unroll
        for (int iW = 0; iW < 10; iW++)
            acc = fmaf(cL[jW * 10 + iW], Xv[iW], acc);
        Ys[(s * 10 + jW) * PIX_PER_BLOCK + t] = acc;
    }

    __syncthreads();

    // ---------------- stage 2: this role's jW = s ----------------
    float yv[10];
#pragma unroll
    for (int iH = 0; iH < 10; iH++)
        yv[iH] = Ys[(iH * 10 + s) * PIX_PER_BLOCK + t];

    const size_t base2 = (size_t)(b * HPIX + hc) * WPIX + s * WC + wc;

#pragma unroll
    for (int jH = 0; jH < 10; jH++) {
        const size_t off = base2 + (size_t)jH * (HC * (size_t)WPIX);
        float z = __ldg(x + off);                 // identity (L1 hit)
#pragma unroll
        for (int iH = 0; iH < 10; iH++)
            z = fmaf(cR[iH * 10 + jH], yv[iH], z);
        out[off] = z;
    }
}

extern "C" void kernel_launch(void* const* d_in, const int* in_sizes, int n_in,
                              void* d_out, int out_size)
{
    const float* x  = (const float*)d_in[0];
    const float* lm = (const float*)d_in[1];
    const float* rm = (const float*)d_in[2];
    float* out = (float*)d_out;

    cudaMemcpyToSymbolAsync(cL, lm, 100 * sizeof(float), 0,
                            cudaMemcpyDeviceToDevice, 0);
    cudaMemcpyToSymbolAsync(cR, rm, 100 * sizeof(float), 0,
                            cudaMemcpyDeviceToDevice, 0);

    cudaFuncSetAttribute(reset_layer_kernel,
                         cudaFuncAttributeMaxDynamicSharedMemorySize, SMEM_BYTES);

    const int grid = PIX_TOTAL / PIX_PER_BLOCK;   // 10000
    reset_layer_kernel<<<grid, THREADS, SMEM_BYTES>>>(x, out);
}

// round 5
// speedup vs baseline: 1.2079x; 1.2079x over previous
#include <cuda_runtime.h>

// reset_layer: x (16,2000,2000) f32, leftm (10,10), rightm (10,10), bs=10.
// out[b, jH*200+hc, jW*200+wc] = x[...] + sum_{iH,iW} R[iH,jH]*L[jW,iW]*x[b, iH*200+hc, iW*200+wc]
//
// Two-stage fused (20 FMA/element):
//   stage1: Y[iH][jW] = sum_iW L[jW,iW] * X[iH][iW]
//   stage2: Z[jH][jW] = X[jH][jW] + sum_iH R[iH,jH] * Y[iH][jW]
//
// R4 change: coefficient loads (LDC, floor 8 cyc/SMSP on sm_103a) are a
// co-limiter with DRAM; they amortize over pixels-per-thread. Back to float4
// (4 pixels/thread: 5 LDC per element, half of R2) but with STREAMING
// accumulators so live regs stay ~56 (R0 held both arrays -> 96 regs).
// 320 threads, __launch_bounds__(320,3): 64-reg cap, 30 warps/SM, 153.6 KB smem.

#define NBATCH   16
#define HPIX     2000
#define WPIX     2000
#define HC       200
#define WC       200
#define PIX_TOTAL (NBATCH * HC * WC)      // 640000
#define PIX_PER_BLOCK 128                 // 32 float4-quads
#define THREADS  320
#define SMEM_BYTES (100 * PIX_PER_BLOCK * 4)   // Ys: 51200 B

__constant__ float cL[100];
__constant__ float cR[100];

extern "C" __global__ void __launch_bounds__(THREADS, 3)
reset_layer_kernel(const float* __restrict__ x,
                   float* __restrict__ out)
{
    extern __shared__ float smem[];
    float4* Ys4 = reinterpret_cast<float4*>(smem);   // [10][10][32] float4

    const int tid = threadIdx.x;
    const int s   = tid >> 5;   // warp = role (iH in stage 1, jW in stage 2)
    const int t   = tid & 31;   // pixel-quad slot 0..31

    // quad of 4 consecutive pixels; wc stays a multiple of 4, never crosses
    // a 200-wide chunk boundary (200 % 4 == 0)
    const int q  = blockIdx.x * PIX_PER_BLOCK + t * 4;
    const int b  = q / (HC * WC);
    const int r  = q - b * (HC * WC);
    const int hc = r / WC;
    const int wc = r - hc * WC;

    // ---------------- stage 1: this warp's iH = s ----------------
    const float* xrow = x + (size_t)(b * HPIX + s * HC + hc) * WPIX + wc;

    float4 Xv[10];
#pragma unroll
    for (int iW = 0; iW < 10; iW++)
        Xv[iW] = *reinterpret_cast<const float4*>(xrow + iW * WC);

#pragma unroll
    for (int jW = 0; jW < 10; jW++) {
        float4 acc = make_float4(0.f, 0.f, 0.f, 0.f);
#pragma unroll
        for (int iW = 0; iW < 10; iW++) {
            const float l = cL[jW * 10 + iW];
            acc.x = fmaf(l, Xv[iW].x, acc.x);
            acc.y = fmaf(l, Xv[iW].y, acc.y);
            acc.z = fmaf(l, Xv[iW].z, acc.z);
            acc.w = fmaf(l, Xv[iW].w, acc.w);
        }
        Ys4[(s * 10 + jW) * 32 + t] = acc;
    }

    __syncthreads();

    // ---------------- stage 2: this warp's jW = s ----------------
    float4 yv[10];
#pragma unroll
    for (int iH = 0; iH < 10; iH++)
        yv[iH] = Ys4[(iH * 10 + s) * 32 + t];

    const size_t base2 = (size_t)(b * HPIX + hc) * WPIX + s * WC + wc;

#pragma unroll
    for (int jH = 0; jH < 10; jH++) {
        const size_t off = base2 + (size_t)jH * (HC * (size_t)WPIX);
        float4 z = *reinterpret_cast<const float4*>(x + off);   // identity (L1 hit)
#pragma unroll
        for (int iH = 0; iH < 10; iH++) {
            const float rr = cR[iH * 10 + jH];
            z.x = fmaf(rr, yv[iH].x, z.x);
            z.y = fmaf(rr, yv[iH].y, z.y);
            z.z = fmaf(rr, yv[iH].z, z.z);
            z.w = fmaf(rr, yv[iH].w, z.w);
        }
        *reinterpret_cast<float4*>(out + off) = z;
    }
}

extern "C" void kernel_launch(void* const* d_in, const int* in_sizes, int n_in,
                              void* d_out, int out_size)
{
    const float* x  = (const float*)d_in[0];
    const float* lm = (const float*)d_in[1];
    const float* rm = (const float*)d_in[2];
    float* out = (float*)d_out;

    cudaMemcpyToSymbolAsync(cL, lm, 100 * sizeof(float), 0,
                            cudaMemcpyDeviceToDevice, 0);
    cudaMemcpyToSymbolAsync(cR, rm, 100 * sizeof(float), 0,
                            cudaMemcpyDeviceToDevice, 0);

    cudaFuncSetAttribute(reset_layer_kernel,
                         cudaFuncAttributeMaxDynamicSharedMemorySize, SMEM_BYTES);

    const int grid = PIX_TOTAL / PIX_PER_BLOCK;   // 5000
    reset_layer_kernel<<<grid, THREADS, SMEM_BYTES>>>(x, out);
}

// round 7
// speedup vs baseline: 1.2254x; 1.0145x over previous
#include <cuda_runtime.h>

// reset_layer: x (16,2000,2000) f32, leftm (10,10), rightm (10,10), bs=10.
// out[b, jH*200+hc, jW*200+wc] = x[...] + sum_{iH,iW} R[iH,jH]*L[jW,iW]*x[b, iH*200+hc, iW*200+wc]
//
// Two-stage fused (20 FMA/element):
//   stage1: Y[iH][jW] = sum_iW L[jW,iW] * X[iH][iW]
//   stage2: Z[jH][jW] = X[jH][jW] + sum_iH R[iH,jH] * Y[iH][jW]
//
// R5 change: the hidden roof was the CONSTANT PORT. 200 scalar LDC/thread at
// the 8-cyc/SMSP GPR-dest floor ~= 135K cyc/SMSP ~= whole kernel duration.
// Now coefficient rows load as vectors (LDC.128/LDC.64, floor is per
// instruction): 60 LDC/thread. Stage 2 restructured iH-outer (z[10] array)
// so R is consumed row-contiguously like L.

#define NBATCH   16
#define HPIX     2000
#define WPIX     2000
#define HC       200
#define WC       200
#define PIX_TOTAL (NBATCH * HC * WC)      // 640000
#define PIX_PER_BLOCK 128                 // 32 float4-quads
#define THREADS  320
#define SMEM_BYTES (100 * PIX_PER_BLOCK * 4)   // Ys: 51200 B

__constant__ __align__(16) float cL[100];
__constant__ __align__(16) float cR[100];

// Load row r (compile-time) of a 10x10 row-major matrix in constant memory
// into registers, using wide LDC. Row byte base = 40*r:
//   r even: base 16-aligned  -> f4 @ +0, f4 @ +16, f2 @ +32
//   r odd : base 8-aligned   -> f2 @ +0, f4 @ +8 (16-al.), f4 @ +24 (16-al.)
__device__ __forceinline__ void load_row(const float* __restrict__ mat, int r,
                                         float c[10])
{
    const char* base = (const char*)mat + r * 40;
    if ((r & 1) == 0) {
        float4 a = *(const float4*)(base);
        float4 bq = *(const float4*)(base + 16);
        float2 d = *(const float2*)(base + 32);
        c[0]=a.x; c[1]=a.y; c[2]=a.z; c[3]=a.w;
        c[4]=bq.x; c[5]=bq.y; c[6]=bq.z; c[7]=bq.w;
        c[8]=d.x; c[9]=d.y;
    } else {
        float2 d = *(const float2*)(base);
        float4 a = *(const float4*)(base + 8);
        float4 bq = *(const float4*)(base + 24);
        c[0]=d.x; c[1]=d.y;
        c[2]=a.x; c[3]=a.y; c[4]=a.z; c[5]=a.w;
        c[6]=bq.x; c[7]=bq.y; c[8]=bq.z; c[9]=bq.w;
    }
}

extern "C" __global__ void __launch_bounds__(THREADS, 3)
reset_layer_kernel(const float* __restrict__ x,
                   float* __restrict__ out)
{
    extern __shared__ float smem[];
    float4* Ys4 = reinterpret_cast<float4*>(smem);   // [10][10][32] float4

    const int tid = threadIdx.x;
    const int s   = tid >> 5;   // warp = role (iH in stage 1, jW in stage 2)
    const int t   = tid & 31;   // pixel-quad slot 0..31

    const int q  = blockIdx.x * PIX_PER_BLOCK + t * 4;
    const int b  = q / (HC * WC);
    const int r  = q - b * (HC * WC);
    const int hc = r / WC;
    const int wc = r - hc * WC;

    // ---------------- stage 1: this warp's iH = s ----------------
    const float* xrow = x + (size_t)(b * HPIX + s * HC + hc) * WPIX + wc;

    float4 Xv[10];
#pragma unroll
    for (int iW = 0; iW < 10; iW++)
        Xv[iW] = *reinterpret_cast<const float4*>(xrow + iW * WC);

#pragma unroll
    for (int jW = 0; jW < 10; jW++) {
        float c[10];
        load_row(cL, jW, c);                       // row jW of L
        float4 acc = make_float4(0.f, 0.f, 0.f, 0.f);
#pragma unroll
        for (int iW = 0; iW < 10; iW++) {
            acc.x = fmaf(c[iW], Xv[iW].x, acc.x);
            acc.y = fmaf(c[iW], Xv[iW].y, acc.y);
            acc.z = fmaf(c[iW], Xv[iW].z, acc.z);
            acc.w = fmaf(c[iW], Xv[iW].w, acc.w);
        }
        Ys4[(s * 10 + jW) * 32 + t] = acc;
    }

    __syncthreads();

    // ---------------- stage 2: this warp's jW = s ----------------
    const size_t base2 = (size_t)(b * HPIX + hc) * WPIX + s * WC + wc;

    float4 z[10];
#pragma unroll
    for (int jH = 0; jH < 10; jH++)   // init with identity (L2 hit)
        z[jH] = *reinterpret_cast<const float4*>(
                    x + base2 + (size_t)jH * (HC * (size_t)WPIX));

#pragma unroll
    for (int iH = 0; iH < 10; iH++) {
        float c[10];
        load_row(cR, iH, c);                       // row iH of R (c[jH] = R[iH,jH])
        const float4 yv = Ys4[(iH * 10 + s) * 32 + t];
#pragma unroll
        for (int jH = 0; jH < 10; jH++) {
            z[jH].x = fmaf(c[jH], yv.x, z[jH].x);
            z[jH].y = fmaf(c[jH], yv.y, z[jH].y);
            z[jH].z = fmaf(c[jH], yv.z, z[jH].z);
            z[jH].w = fmaf(c[jH], yv.w, z[jH].w);
        }
    }

#pragma unroll
    for (int jH = 0; jH < 10; jH++)
        *reinterpret_cast<float4*>(
            out + base2 + (size_t)jH * (HC * (size_t)WPIX)) = z[jH];
}

extern "C" void kernel_launch(void* const* d_in, const int* in_sizes, int n_in,
                              void* d_out, int out_size)
{
    const float* x  = (const float*)d_in[0];
    const float* lm = (const float*)d_in[1];
    const float* rm = (const float*)d_in[2];
    float* out = (float*)d_out;

    cudaMemcpyToSymbolAsync(cL, lm, 100 * sizeof(float), 0,
                            cudaMemcpyDeviceToDevice, 0);
    cudaMemcpyToSymbolAsync(cR, rm, 100 * sizeof(float), 0,
                            cudaMemcpyDeviceToDevice, 0);

    cudaFuncSetAttribute(reset_layer_kernel,
                         cudaFuncAttributeMaxDynamicSharedMemorySize, SMEM_BYTES);

    const int grid = PIX_TOTAL / PIX_PER_BLOCK;   // 5000
    reset_layer_kernel<<<grid, THREADS, SMEM_BYTES>>>(x, out);
}